// round 10
// baseline (speedup 1.0000x reference)
#include <cuda_runtime.h>
#include <cstdint>

#define HID   32
#define NCOL  224
#define TPB   128     // 4 warps, 1 sample per block
#define NSTEP 2047
#define NB    512
#define SEQ   2048
#define NTY   20
#define BETA  0.1f

typedef unsigned long long ull;

__device__ __forceinline__ unsigned su32(const void* p) {
    return (unsigned)__cvta_generic_to_shared(p);
}
__device__ __forceinline__ void ffma2(ull& d, ull a, ull b) {
    asm("fma.rn.f32x2 %0, %1, %2, %0;" : "+l"(d) : "l"(a), "l"(b));
}
__device__ __forceinline__ ull fadd2(ull a, ull b) {
    ull d; asm("add.rn.f32x2 %0, %1, %2;" : "=l"(d) : "l"(a), "l"(b)); return d;
}
__device__ __forceinline__ ull pack2(float a, float b) {
    ull d; asm("mov.b64 %0, {%1, %2};" : "=l"(d) : "f"(a), "f"(b)); return d;
}
__device__ __forceinline__ float sum2(ull v) {
    float a, b; asm("mov.b64 {%0, %1}, %2;" : "=f"(a), "=f"(b) : "l"(v));
    return a + b;
}
__device__ __forceinline__ void lds128(ull& a, ull& b, unsigned addr) {
    asm volatile("ld.shared.v2.u64 {%0, %1}, [%2];" : "=l"(a), "=l"(b) : "r"(addr));
}

__device__ __forceinline__ float tanh_fast(float x) {
    float e = __expf(-2.f * fabsf(x));          // overflow-safe: e in (0,1]
    float t = __fdividef(1.f - e, 1.f + e);
    return copysignf(t, x);
}
__device__ __forceinline__ float sigmoid_fast(float x) {
    return __fdividef(1.f, 1.f + __expf(-x));
}

__global__ __launch_bounds__(TPB, 4)
void hawkes_kernel(const int* __restrict__ types,
                   const float* __restrict__ dtime,
                   const float* __restrict__ emb,
                   const float* __restrict__ W,
                   const float* __restrict__ bvec,
                   float* __restrict__ out)
{
    __shared__ float s_gx[NTY * NCOL];            // x-side pre-activation (incl. bias)
    __shared__ float s_act[2][NCOL];              // double-buffered; slot 6 holds edt
    __shared__ __align__(16) float s_hw[4][HID];  // warp-private h
    __shared__ float s_emb[NTY * HID];
    __shared__ unsigned char s_ty[NSTEP + 1];
    __shared__ float s_dt[NSTEP];

    const int tid  = threadIdx.x;
    const int warp = tid >> 5;          // 0..3, warp-uniform
    const int lane = tid & 31;
    const int bs   = blockIdx.x;

    // ---- prologue ----
    for (int i = tid; i < NTY * HID; i += TPB) s_emb[i] = emb[i];
    for (int t = tid; t < NSTEP; t += TPB) {
        s_ty[t] = (unsigned char)types[bs * SEQ + t];
        s_dt[t] = dtime[bs * SEQ + t + 1];
    }
    s_hw[warp][lane] = 0.f;
    __syncthreads();

    // ---- column ownership: w0={i,f}, w1={z,o}, w2={ib,fb}, w3={delta} ----
    const int  gA   = 2 * warp;                  // first gate (0,2,4,6)
    const bool has2 = (warp < 3);
    const int  colA = gA * HID + lane;
    const int  colB = has2 ? (gA + 1) * HID + lane : colA;

    // build gx table entries for my columns
    {
        float wxa[HID], wxb[HID];
        #pragma unroll
        for (int k = 0; k < HID; k++) {
            wxa[k] = W[k * NCOL + colA];
            wxb[k] = W[k * NCOL + colB];
        }
        const float ba = bvec[colA], bb = bvec[colB];
        for (int ty = 0; ty < NTY; ty++) {
            float aa = ba, ab = bb;
            #pragma unroll
            for (int k = 0; k < HID; k++) {
                const float e = s_emb[ty * HID + k];
                aa += e * wxa[k];
                ab += e * wxb[k];
            }
            s_gx[ty * NCOL + colA] = aa;
            if (has2) s_gx[ty * NCOL + colB] = ab;
        }
    }
    // recurrent weights, k-packed
    ull wA[HID / 2], wB[HID / 2];
    #pragma unroll
    for (int q = 0; q < HID / 2; q++) {
        wA[q] = pack2(W[(HID + 2 * q) * NCOL + colA],
                      W[(HID + 2 * q + 1) * NCOL + colA]);
        wB[q] = pack2(W[(HID + 2 * q) * NCOL + colB],
                      W[(HID + 2 * q + 1) * NCOL + colB]);
    }
    __syncthreads();

    const unsigned hb = su32(&s_hw[warp][0]);
    float c = 0.f, cbar = 0.f;                    // replicated in all 4 warps

    const size_t O1 = (size_t)NSTEP * NB * HID;
    size_t obase = (size_t)bs * HID + lane;

    for (int t = 0; t < NSTEP; t++) {
        const int ty  = s_ty[t];
        const int buf = t & 1;

        // matvec: 8 broadcast LDS.128 feed both columns (packed fp32x2)
        ull aA0 = 0, aA1 = 0, aB0 = 0, aB1 = 0;
        #pragma unroll
        for (int q = 0; q < 8; q++) {
            ull hA, hB;
            lds128(hA, hB, hb + q * 16);          // warp-private broadcast
            ffma2(aA0, hA, wA[2 * q]);
            ffma2(aA1, hB, wA[2 * q + 1]);
            if (has2) {
                ffma2(aB0, hA, wB[2 * q]);
                ffma2(aB1, hB, wB[2 * q + 1]);
            }
        }
        const float gAv = s_gx[ty * NCOL + colA] + sum2(fadd2(aA0, aA1));
        const float gBv = has2 ? (s_gx[ty * NCOL + colB] + sum2(fadd2(aB0, aB1))) : 0.f;

        // activations — warp-uniform, MUFU-balanced
        float actA, actB = 0.f;
        if (warp == 0) {                          // i, f
            actA = sigmoid_fast(gAv);
            actB = sigmoid_fast(gBv);
        } else if (warp == 1) {                   // z (tanh), o
            actA = tanh_fast(gAv);
            actB = sigmoid_fast(gBv);
            out[4 * O1 + obase] = actB;           // gate_out (o_g)
        } else if (warp == 2) {                   // ib, fb
            actA = sigmoid_fast(gAv);
            actB = sigmoid_fast(gBv);
        } else {                                  // delta -> edt
            const float y = BETA * gAv;
            const float del = (fmaxf(y, 0.f) + __logf(1.f + __expf(-fabsf(y)))) * (1.f / BETA);
            out[3 * O1 + obase] = del;            // decay_out
            actA = __expf(-del * s_dt[t]);        // publish exp(-delta*dt) in slot 6
        }
        s_act[buf][colA] = actA;
        if (has2) s_act[buf][colB] = actB;
        __syncthreads();                          // the only block barrier per step

        // 4-way replicated combine (bitwise identical in all warps)
        const float* A = s_act[buf];
        const float ig  = A[lane];
        const float fg  = A[HID + lane];
        const float zg  = A[2 * HID + lane];
        const float og  = A[3 * HID + lane];
        const float ibg = A[4 * HID + lane];
        const float fbg = A[5 * HID + lane];
        const float edt = A[6 * HID + lane];

        const float cn  = fmaf(fg, c, ig * zg);
        const float cbn = fmaf(fbg, cbar, ibg * zg);
        const float ct  = fmaf(cn - cbn, edt, cbn);
        const float hn  = og * tanh_fast(ct);
        c = ct; cbar = cbn;

        s_hw[warp][lane] = hn;                    // warp-private; no block sync needed
        __syncwarp();

        if      (warp == 0) out[obase]          = hn;    // h_out
        else if (warp == 2) out[O1 + obase]     = cn;    // c_out
        else if (warp == 3) out[2 * O1 + obase] = cbn;   // c_bar_out
        obase += (size_t)NB * HID;
    }
}

extern "C" void kernel_launch(void* const* d_in, const int* in_sizes, int n_in,
                              void* d_out, int out_size)
{
    const int*   types = (const int*)d_in[0];
    const float* dtime = (const float*)d_in[1];
    const float* emb   = (const float*)d_in[2];
    const float* W     = (const float*)d_in[3];
    const float* bvec  = (const float*)d_in[4];
    hawkes_kernel<<<NB, TPB>>>(types, dtime, emb, W, bvec, (float*)d_out);
}